// round 11
// baseline (speedup 1.0000x reference)
#include <cuda_runtime.h>

// LocalSpatialEncoding: enc=[rel(3),|rel|] -> (W1,BN,ReLU)[4] -> (W2,BN,ReLU)[8]
// B=8,N=16384,K=16. Output (B,N,K,8) fp32.
// R11 (= R10 cleaned, resubmit after infra failure): R8 compute skeleton,
// output path rebuilt: block stages its 512-point output (16 KB) in smem in
// FINAL layout, then ONE cp.async.bulk TMA store writes it to gmem.
// No readback LDS, no STG — ~32 fewer L1 wavefronts per warp vs R8.

#define LSE_EPS 1e-5f
#define TOTAL    (8 * 16384 * 16)   // 2097152 points
#define THREADS  256
#define PTS_BLK  512                // points per block (2 per thread)
#define STAGE_F4 (PTS_BLK * 2)      // 1024 float4 = 16 KB

__device__ __forceinline__ float sqrt_ap(float x) {
    float r; asm("sqrt.approx.f32 %0,%1;" : "=f"(r) : "f"(x)); return r;
}
__device__ __forceinline__ unsigned smem_u32(const void* p) {
    unsigned a;
    asm("{ .reg .u64 t; cvta.to.shared.u64 t, %1; cvt.u32.u64 %0, t; }"
        : "=r"(a) : "l"(p));
    return a;
}

__global__ void __launch_bounds__(THREADS)
lse_main(const float* __restrict__ coords,
         const float* __restrict__ nbr,
         const float* __restrict__ W1, const float* __restrict__ g1,
         const float* __restrict__ b1, const float* __restrict__ m1,
         const float* __restrict__ v1,
         const float* __restrict__ W2, const float* __restrict__ g2,
         const float* __restrict__ b2, const float* __restrict__ m2,
         const float* __restrict__ v2,
         float* __restrict__ out)
{
    // Folded weights, float4-addressable:
    //   w4[0..3] = W1' rows   w4[4] = t1   w4[5..12] = W2' rows   w4[13,14] = t2
    __shared__ __align__(16) float  sw[60];
    __shared__ __align__(16) float4 stage[STAGE_F4];   // final-layout block output

    int t = threadIdx.x;
    if (t < 16) {
        int o = t >> 2;
        float s = g1[o] * rsqrtf(v1[o] + LSE_EPS);
        sw[t] = W1[t] * s;
        if ((t & 3) == 0) sw[16 + o] = b1[o] - m1[o] * s;
    } else if (t < 48) {
        int i = t - 16;
        int o = i >> 2;
        float s = g2[o] * rsqrtf(v2[o] + LSE_EPS);
        sw[20 + i] = W2[i] * s;
        if ((i & 3) == 0) sw[52 + o] = b2[o] - m2[o] * s;
    }
    __syncthreads();
    const float4* w4 = reinterpret_cast<const float4*>(sw);

    float4 t1v = w4[4];
    const float* t1p = reinterpret_cast<const float*>(&t1v);
    float4 t2a = w4[13], t2b = w4[14];
    const float* t2p0 = reinterpret_cast<const float*>(&t2a);
    const float* t2p1 = reinterpret_cast<const float*>(&t2b);

    int base = blockIdx.x * PTS_BLK;

    // Thread computes points base+t and base+t+256. Scalar neighbor loads
    // (3 per point) are warp-coalesced (12B/lane contiguous); center coord
    // broadcast across 16 consecutive lanes.
#pragma unroll
    for (int pp = 0; pp < 2; pp++) {
        int p = base + t + pp * 256;

        const float* nb = nbr + (size_t)p * 3;
        float n0 = __ldg(nb + 0);
        float n1 = __ldg(nb + 1);
        float n2 = __ldg(nb + 2);

        const float* cp = coords + (size_t)(p >> 4) * 3;
        float rx = n0 - __ldg(cp + 0);
        float ry = n1 - __ldg(cp + 1);
        float rz = n2 - __ldg(cp + 2);
        float d  = sqrt_ap(fmaf(rx, rx, fmaf(ry, ry, rz * rz)));

        float h[4];
#pragma unroll
        for (int o = 0; o < 4; o++) {
            float4 w = w4[o];
            h[o] = fmaxf(fmaf(rx, w.x, fmaf(ry, w.y, fmaf(rz, w.z, fmaf(d, w.w, t1p[o])))), 0.0f);
        }

        float yv[8];
#pragma unroll
        for (int o = 0; o < 8; o++) {
            float4 w = w4[5 + o];
            float bias = (o < 4) ? t2p0[o] : t2p1[o - 4];
            yv[o] = fmaxf(fmaf(h[0], w.x, fmaf(h[1], w.y, fmaf(h[2], w.z, fmaf(h[3], w.w, bias)))), 0.0f);
        }

        // Final layout: local point (t + 256*pp) occupies 2 consecutive float4s.
        int slot = 2 * (t + pp * 256);
        stage[slot + 0] = make_float4(yv[0], yv[1], yv[2], yv[3]);
        stage[slot + 1] = make_float4(yv[4], yv[5], yv[6], yv[7]);
    }

    __syncthreads();

    // ---- One 16 KB TMA bulk store of the block's final-layout output ----
    if (t == 0) {
        asm volatile("fence.proxy.async.shared::cta;" ::: "memory");
        float* dst = out + (size_t)base * 8;
        unsigned s = smem_u32(stage);
        asm volatile(
            "cp.async.bulk.global.shared::cta.bulk_group [%0], [%1], %2;"
            :: "l"(dst), "r"(s), "r"((unsigned)(STAGE_F4 * 16)) : "memory");
        asm volatile("cp.async.bulk.commit_group;" ::: "memory");
        asm volatile("cp.async.bulk.wait_group.read 0;" ::: "memory");
    }
}

extern "C" void kernel_launch(void* const* d_in, const int* in_sizes, int n_in,
                              void* d_out, int out_size)
{
    const float* coords = (const float*)d_in[0];
    const float* nbr    = (const float*)d_in[1];
    const float* W1     = (const float*)d_in[2];
    const float* g1     = (const float*)d_in[3];
    const float* b1     = (const float*)d_in[4];
    const float* m1     = (const float*)d_in[5];
    const float* v1     = (const float*)d_in[6];
    const float* W2     = (const float*)d_in[7];
    const float* g2     = (const float*)d_in[8];
    const float* b2     = (const float*)d_in[9];
    const float* m2     = (const float*)d_in[10];
    const float* v2     = (const float*)d_in[11];
    float* out = (float*)d_out;

    int blocks = TOTAL / PTS_BLK;   // 4096
    lse_main<<<blocks, THREADS>>>(coords, nbr, W1, g1, b1, m1, v1,
                                  W2, g2, b2, m2, v2, out);
}

// round 13
// speedup vs baseline: 1.2457x; 1.2457x over previous
#include <cuda_runtime.h>
#include <cuda.h>

// LocalSpatialEncoding: enc=[rel(3),|rel|] -> (W1,BN,ReLU)[4] -> (W2,BN,ReLU)[8]
// B=8,N=16384,K=16. Output (B,N,K,8) fp32.
// R13 (= R12 with two bug fixes):
//   1. stage region forced to 1024B SMEM alignment (TMA SW128 de-swizzle keys
//      off absolute addr bits [7:10) — misaligned base scrambles the pattern).
//   2. fence.proxy.async AFTER all STS, per-lane, before __syncwarp + TMA.
// Per-warp SW128 stage (STS.128 minimal 4 phases) + one 2KB tensor.2d store.
// Fallback: exact R8 kernel if tensor-map encode is unavailable.

#define LSE_EPS 1e-5f
#define TOTAL   (8 * 16384 * 16)   // 2097152 points
#define THREADS 256
#define WARPS   8
#define PTW     64                 // points per warp (32 lanes * 2)

__device__ __forceinline__ float sqrt_ap(float x) {
    float r; asm("sqrt.approx.f32 %0,%1;" : "=f"(r) : "f"(x)); return r;
}
__device__ __forceinline__ unsigned smem_u32(const void* p) {
    unsigned a;
    asm("{ .reg .u64 t; cvta.to.shared.u64 t, %1; cvt.u32.u64 %0, t; }"
        : "=r"(a) : "l"(p));
    return a;
}

// ---------------- shared compute helpers ------------------------------------
__device__ __forceinline__ void fold_weights(
    float* sw, int t,
    const float* W1, const float* g1, const float* b1, const float* m1, const float* v1,
    const float* W2, const float* g2, const float* b2, const float* m2, const float* v2)
{
    if (t < 16) {
        int o = t >> 2;
        float s = g1[o] * rsqrtf(v1[o] + LSE_EPS);
        sw[t] = W1[t] * s;
        if ((t & 3) == 0) sw[16 + o] = b1[o] - m1[o] * s;
    } else if (t < 48) {
        int i = t - 16;
        int o = i >> 2;
        float s = g2[o] * rsqrtf(v2[o] + LSE_EPS);
        sw[20 + i] = W2[i] * s;
        if ((i & 3) == 0) sw[52 + o] = b2[o] - m2[o] * s;
    }
}

// Computes the 2-point MLP for thread-global index g (points 2g, 2g+1).
__device__ __forceinline__ void compute_two_points(
    int g, const float* __restrict__ coords, const float* __restrict__ nbr,
    const float4* w4, float* ya, float* yb)
{
    const float2* nb2 = reinterpret_cast<const float2*>(nbr) + (size_t)g * 3;
    float2 va = __ldg(nb2 + 0);
    float2 vb = __ldg(nb2 + 1);
    float2 vc = __ldg(nb2 + 2);

    const float* cp = coords + (size_t)(g >> 3) * 3;
    float c0 = __ldg(cp + 0), c1 = __ldg(cp + 1), c2 = __ldg(cp + 2);

    // pt0 = (va.x, va.y, vb.x), pt1 = (vb.y, vc.x, vc.y)
    float ax = va.x - c0, ay = va.y - c1, az = vb.x - c2;
    float bx = vb.y - c0, by = vc.x - c1, bz = vc.y - c2;
    float da = sqrt_ap(fmaf(ax, ax, fmaf(ay, ay, az * az)));
    float db = sqrt_ap(fmaf(bx, bx, fmaf(by, by, bz * bz)));

    float4 t1v = w4[4];
    const float* t1p = reinterpret_cast<const float*>(&t1v);
    float ha[4], hb[4];
#pragma unroll
    for (int o = 0; o < 4; o++) {
        float4 w = w4[o];
        ha[o] = fmaxf(fmaf(ax, w.x, fmaf(ay, w.y, fmaf(az, w.z, fmaf(da, w.w, t1p[o])))), 0.0f);
        hb[o] = fmaxf(fmaf(bx, w.x, fmaf(by, w.y, fmaf(bz, w.z, fmaf(db, w.w, t1p[o])))), 0.0f);
    }

    float4 t2a = w4[13], t2b = w4[14];
    const float* t2p0 = reinterpret_cast<const float*>(&t2a);
    const float* t2p1 = reinterpret_cast<const float*>(&t2b);
#pragma unroll
    for (int o = 0; o < 8; o++) {
        float4 w = w4[5 + o];
        float bias = (o < 4) ? t2p0[o] : t2p1[o - 4];
        ya[o] = fmaxf(fmaf(ha[0], w.x, fmaf(ha[1], w.y, fmaf(ha[2], w.z, fmaf(ha[3], w.w, bias)))), 0.0f);
        yb[o] = fmaxf(fmaf(hb[0], w.x, fmaf(hb[1], w.y, fmaf(hb[2], w.z, fmaf(hb[3], w.w, bias)))), 0.0f);
    }
}

// ---------------- R13: TMA tensor-store kernel ------------------------------
__global__ void __launch_bounds__(THREADS)
lse_tma(const float* __restrict__ coords,
        const float* __restrict__ nbr,
        const float* __restrict__ W1, const float* __restrict__ g1,
        const float* __restrict__ b1, const float* __restrict__ m1,
        const float* __restrict__ v1,
        const float* __restrict__ W2, const float* __restrict__ g2,
        const float* __restrict__ b2, const float* __restrict__ m2,
        const float* __restrict__ v2,
        const __grid_constant__ CUtensorMap tmap)
{
    __shared__ __align__(16) float sw[60];
    __shared__ char raw[WARPS * 2048 + 1024];   // over-allocated for 1KB alignment

    int t = threadIdx.x;
    fold_weights(sw, t, W1, g1, b1, m1, v1, W2, g2, b2, m2, v2);
    __syncthreads();
    const float4* w4 = reinterpret_cast<const float4*>(sw);

    int g    = blockIdx.x * THREADS + t;   // thread owns points 2g, 2g+1
    int warp = t >> 5;
    int lane = t & 31;

    float ya[8], yb[8];
    compute_two_points(g, coords, nbr, w4, ya, yb);

    // 1024B-aligned stage base (shared address space), same value in all threads.
    unsigned stg   = (smem_u32(raw) + 1023u) & ~1023u;
    unsigned tile  = stg + warp * 2048u;       // 2048 % 1024 == 0 -> stays aligned

    // Stage in FINAL layout + SW128 swizzle (tile-relative == absolute pattern
    // now that tile is 1024B aligned). Thread's 4 float4s at bytes 64*lane+16j;
    // swizzled STS.128 is 4-phase (minimal).
    unsigned o0 = 64u * lane;
#pragma unroll
    for (int j = 0; j < 4; j++) {
        unsigned o  = o0 + 16u * j;
        unsigned so = o ^ ((o >> 3) & 0x70);
        float4 v = (j == 0) ? make_float4(ya[0], ya[1], ya[2], ya[3])
                 : (j == 1) ? make_float4(ya[4], ya[5], ya[6], ya[7])
                 : (j == 2) ? make_float4(yb[0], yb[1], yb[2], yb[3])
                            : make_float4(yb[4], yb[5], yb[6], yb[7]);
        asm volatile("st.shared.v4.f32 [%0], {%1,%2,%3,%4};"
                     :: "r"(tile + so), "f"(v.x), "f"(v.y), "f"(v.z), "f"(v.w)
                     : "memory");
    }

    // Order: every lane fences its own STS into the async proxy, then warp-sync,
    // then one lane issues the TMA store for the warp's tile.
    asm volatile("fence.proxy.async.shared::cta;" ::: "memory");
    __syncwarp();

    if (lane == 0) {
        int row = (blockIdx.x * WARPS + warp) * 16;   // 16 gmem rows of 128B per warp
        const CUtensorMap* tp = &tmap;
        asm volatile(
            "cp.async.bulk.tensor.2d.global.shared::cta.tile.bulk_group "
            "[%0, {%1, %2}], [%3];"
            :: "l"(tp), "r"(0), "r"(row), "r"(tile) : "memory");
        asm volatile("cp.async.bulk.commit_group;" ::: "memory");
        asm volatile("cp.async.bulk.wait_group.read 0;" ::: "memory");
    }
}

// ---------------- Fallback: exact R8 kernel (proven 17.1us main) ------------
#define STR 68
__global__ void __launch_bounds__(THREADS)
lse_r8(const float* __restrict__ coords,
       const float* __restrict__ nbr,
       const float* __restrict__ W1, const float* __restrict__ g1,
       const float* __restrict__ b1, const float* __restrict__ m1,
       const float* __restrict__ v1,
       const float* __restrict__ W2, const float* __restrict__ g2,
       const float* __restrict__ b2, const float* __restrict__ m2,
       const float* __restrict__ v2,
       float* __restrict__ out)
{
    __shared__ __align__(16) float sw[60];
    __shared__ __align__(16) float sbuf[WARPS][8][STR];

    int t = threadIdx.x;
    fold_weights(sw, t, W1, g1, b1, m1, v1, W2, g2, b2, m2, v2);
    __syncthreads();
    const float4* w4 = reinterpret_cast<const float4*>(sw);

    int g    = blockIdx.x * THREADS + t;
    int warp = t >> 5;
    int lane = t & 31;

    float ya[8], yb[8];
    compute_two_points(g, coords, nbr, w4, ya, yb);

#pragma unroll
    for (int o = 0; o < 8; o++)
        *reinterpret_cast<float2*>(&sbuf[warp][o][2 * lane]) = make_float2(ya[o], yb[o]);
    __syncwarp();

    int warpbase = blockIdx.x * (THREADS * 2) + warp * PTW;
    float4* o4 = reinterpret_cast<float4*>(out) + (size_t)warpbase * 2;
#pragma unroll
    for (int k = 0; k < 4; k++) {
        int f  = lane + 32 * k;
        int pt = f >> 1;
        int cb = (f & 1) * 4;
        float4 v;
        v.x = sbuf[warp][cb + 0][pt];
        v.y = sbuf[warp][cb + 1][pt];
        v.z = sbuf[warp][cb + 2][pt];
        v.w = sbuf[warp][cb + 3][pt];
        o4[f] = v;
    }
}

// ---------------- host ------------------------------------------------------
typedef CUresult (*tmap_encode_fn)(
    CUtensorMap*, CUtensorMapDataType, cuuint32_t, void*,
    const cuuint64_t*, const cuuint64_t*, const cuuint32_t*, const cuuint32_t*,
    CUtensorMapInterleave, CUtensorMapSwizzle, CUtensorMapL2promotion,
    CUtensorMapFloatOOBfill);

extern "C" void kernel_launch(void* const* d_in, const int* in_sizes, int n_in,
                              void* d_out, int out_size)
{
    const float* coords = (const float*)d_in[0];
    const float* nbr    = (const float*)d_in[1];
    const float* W1     = (const float*)d_in[2];
    const float* g1     = (const float*)d_in[3];
    const float* b1     = (const float*)d_in[4];
    const float* m1     = (const float*)d_in[5];
    const float* v1     = (const float*)d_in[6];
    const float* W2     = (const float*)d_in[7];
    const float* g2     = (const float*)d_in[8];
    const float* b2     = (const float*)d_in[9];
    const float* m2     = (const float*)d_in[10];
    const float* v2     = (const float*)d_in[11];
    float* out = (float*)d_out;

    int blocks = TOTAL / (THREADS * 2);   // 4096

    // Build the output tensor map (CPU-only; safe under graph capture).
    tmap_encode_fn encode = nullptr;
    cudaDriverEntryPointQueryResult qr = cudaDriverEntryPointSymbolNotFound;
#if CUDART_VERSION >= 12050
    cudaGetDriverEntryPointByVersion("cuTensorMapEncodeTiled", (void**)&encode,
                                     12000, cudaEnableDefault, &qr);
#else
    cudaGetDriverEntryPoint("cuTensorMapEncodeTiled", (void**)&encode,
                            cudaEnableDefault, &qr);
#endif

    bool tma_ok = false;
    CUtensorMap tmap;
    if (encode && qr == cudaDriverEntryPointSuccess) {
        // Output viewed as [32 floats][524288 rows], 128B rows, SW128.
        cuuint64_t dims[2]    = {32, (cuuint64_t)TOTAL * 32 / 128};  // 524288 rows
        cuuint64_t strides[1] = {128};
        cuuint32_t box[2]     = {32, 16};     // one warp tile: 16 rows x 128B
        cuuint32_t es[2]      = {1, 1};
        CUresult r = encode(&tmap, CU_TENSOR_MAP_DATA_TYPE_FLOAT32, 2, out,
                            dims, strides, box, es,
                            CU_TENSOR_MAP_INTERLEAVE_NONE,
                            CU_TENSOR_MAP_SWIZZLE_128B,
                            CU_TENSOR_MAP_L2_PROMOTION_L2_128B,
                            CU_TENSOR_MAP_FLOAT_OOB_FILL_NONE);
        tma_ok = (r == CUDA_SUCCESS);
    }

    if (tma_ok) {
        lse_tma<<<blocks, THREADS>>>(coords, nbr, W1, g1, b1, m1, v1,
                                     W2, g2, b2, m2, v2, tmap);
    } else {
        lse_r8<<<blocks, THREADS>>>(coords, nbr, W1, g1, b1, m1, v1,
                                    W2, g2, b2, m2, v2, out);
    }
}